// round 17
// baseline (speedup 1.0000x reference)
#include <cuda_runtime.h>
#include <cuda_bf16.h>
#include <cstdint>

// R17: AR(24) closed-form GEMM, warp-specialized single kernel.
//  warp 4 (producer): 168-step coefficient shfl-recurrence (R12/14/15/16-
//    verified algebra), writes bf16 hi/lo frags into SMEM, arrives a named
//    barrier every 56 steps (3 phases).
//  warps 0-3 (consumers): A frags from 12 direct LDGs (R16-verified mapping),
//    per phase: 7 n-tiles x 6 split-bf16 MMAs, accumulators stored DIRECTLY
//    to gmem (4 full 32B sectors per STG instr -- no SMEM transpose).
//
// Shapes: x [256,336,512] f32, W [24,1] f32, b [1] f32, out [256,168,512] f32

#define ORDER 24
#define T_OUT 168
#define D_DIM 512
#define B_DIM 256
#define S_DIM 336
#define THREADS 160          // 4 consumer warps + 1 producer warp
#define NT 21
#define PH_NT 7

static __device__ __forceinline__ unsigned short bf16_bits(float v) {
    __nv_bfloat16 b = __float2bfloat16(v);
    unsigned short u; __builtin_memcpy(&u, &b, 2); return u;
}
static __device__ __forceinline__ float bf16_val(float v) {
    return __bfloat162float(__float2bfloat16(v));
}
static __device__ __forceinline__ unsigned pack_hi(float v0, float v1) {
    return ((unsigned)bf16_bits(v1) << 16) | (unsigned)bf16_bits(v0);
}
static __device__ __forceinline__ unsigned pack_lo(float v0, float v1) {
    return pack_hi(v0 - bf16_val(v0), v1 - bf16_val(v1));
}

#define MMA_BF16(c, A, b0, b1)                                                \
    asm("mma.sync.aligned.m16n8k16.row.col.f32.bf16.bf16.f32 "                \
        "{%0,%1,%2,%3},{%4,%5,%6,%7},{%8,%9},{%0,%1,%2,%3};"                  \
        : "+f"((c)[0]), "+f"((c)[1]), "+f"((c)[2]), "+f"((c)[3])              \
        : "r"((A)[0]), "r"((A)[1]), "r"((A)[2]), "r"((A)[3]),                 \
          "r"(b0), "r"(b1))

__global__ __launch_bounds__(THREADS)
void ar_ws_kernel(const float* __restrict__ x,
                  const float* __restrict__ W,
                  const float* __restrict__ bias,
                  float* __restrict__ out) {
    // B fragments [nt][ks][lane] as uint4 {bh0,bh1,bl0,bl1}  (21504 B)
    __shared__ __align__(16) uint4 BF[NT * 2 * 32];

    const int tid  = threadIdx.x;
    const int wid  = tid >> 5, lane = tid & 31;
    const int b    = blockIdx.x >> 3;
    const int d0   = (blockIdx.x & 7) << 6;

    unsigned bf_base;
    asm("{ .reg .u64 t; cvta.to.shared.u64 t, %1; cvt.u32.u64 %0, t; }"
        : "=r"(bf_base) : "l"(BF));

    if (wid == 4) {
        // ---------------- producer: coefficient chain -> SMEM frags --------
        const float bval = __ldg(bias);
        const float wlane = (lane < ORDER) ? __ldg(&W[lane]) : 0.0f;
        float m = wlane;
        float beta = 1.0f;
        // lane k -> fragment byte position (R16-verified)
        const int ks  = lane >> 4;
        const int km  = lane & 15;
        const int eps = km >> 3;
        const int rem = km & 7;
        const int qpf = rem >> 1;
        const int dlt = rem & 1;
        const unsigned coff = (unsigned)(ks * 512 + qpf * 16 + eps * 4 + dlt * 2);

        for (int t = 0; t < T_OUT; t++) {
            float c23 = __shfl_sync(0xFFFFFFFFu, m, ORDER - 1);
            float up  = __shfl_up_sync(0xFFFFFFFFu, m, 1);
            float val;
            if (lane < ORDER)       val = m;
            else if (lane == ORDER) val = beta * bval;
            else                    val = 0.0f;
            unsigned short hb = bf16_bits(val);
            unsigned short lb = bf16_bits(val - bf16_val(val));
            unsigned addr = bf_base + (unsigned)((t >> 3) * 1024 + (t & 7) * 64) + coff;
            asm volatile("st.shared.u16 [%0], %1;" :: "r"(addr), "h"(hb));
            asm volatile("st.shared.u16 [%0], %1;" :: "r"(addr + 8), "h"(lb));
            if (lane < ORDER) m = fmaf(c23, wlane, (lane == 0) ? 0.0f : up);
            if (lane == ORDER) beta += c23;
            if (t == 55) {
                __threadfence_block();
                asm volatile("bar.arrive 1, 160;");
            } else if (t == 111) {
                __threadfence_block();
                asm volatile("bar.arrive 2, 160;");
            }
        }
        __threadfence_block();
        asm volatile("bar.arrive 3, 160;");
    } else {
        // ---------------- consumers: A frags + MMA + direct stores ---------
        const int grp = lane >> 2, qp = lane & 3;
        const int r = wid * 16 + grp;

        // A: 12 direct LDGs -> split-bf16 fragment registers (R16-verified)
        float v[2][6];
        {
            const float* xw = x + ((size_t)b * S_DIM + (S_DIM - ORDER)) * D_DIM + d0;
#pragma unroll
            for (int rr = 0; rr < 2; rr++) {
                const float* xr = xw + r + rr * 8;
                const int k0 = 2 * qp;
                v[rr][0] = __ldg(xr + (size_t)(k0)      * D_DIM);
                v[rr][1] = __ldg(xr + (size_t)(k0 + 1)  * D_DIM);
                v[rr][2] = __ldg(xr + (size_t)(k0 + 8)  * D_DIM);
                v[rr][3] = __ldg(xr + (size_t)(k0 + 9)  * D_DIM);
                v[rr][4] = __ldg(xr + (size_t)(k0 + 16) * D_DIM);
                v[rr][5] = __ldg(xr + (size_t)(k0 + 17) * D_DIM);
            }
        }
        uint32_t a[2][2][4];
#pragma unroll
        for (int rr = 0; rr < 2; rr++) {
            a[0][0][0 + rr] = pack_hi(v[rr][0], v[rr][1]);
            a[1][0][0 + rr] = pack_lo(v[rr][0], v[rr][1]);
            a[0][0][2 + rr] = pack_hi(v[rr][2], v[rr][3]);
            a[1][0][2 + rr] = pack_lo(v[rr][2], v[rr][3]);
            a[0][1][0 + rr] = pack_hi(v[rr][4], v[rr][5]);
            a[1][1][0 + rr] = pack_lo(v[rr][4], v[rr][5]);
        }
        {   // k = 24..31 pad: bias column k==24 -> 1.0 (low half of qp==0)
            const unsigned cst = (qp == 0) ? 0x00003F80u : 0u;
            a[0][1][2] = cst; a[0][1][3] = cst;
            a[1][1][2] = 0u;  a[1][1][3] = 0u;
        }

        float* ob = out + (size_t)b * T_OUT * D_DIM + d0 + r;

#pragma unroll 1
        for (int p = 0; p < 3; p++) {
            if (p == 0)      asm volatile("bar.sync 1, 160;" ::: "memory");
            else if (p == 1) asm volatile("bar.sync 2, 160;" ::: "memory");
            else             asm volatile("bar.sync 3, 160;" ::: "memory");

            float acc[PH_NT][4];
#pragma unroll
            for (int nt = 0; nt < PH_NT; nt++)
#pragma unroll
                for (int c = 0; c < 4; c++) acc[nt][c] = 0.0f;

#pragma unroll
            for (int nt = 0; nt < PH_NT; nt++) {
                uint4 f0, f1;
                unsigned ba = bf_base + (unsigned)((p * PH_NT + nt) * 1024 + lane * 16);
                asm("ld.shared.v4.u32 {%0,%1,%2,%3}, [%4];"
                    : "=r"(f0.x), "=r"(f0.y), "=r"(f0.z), "=r"(f0.w) : "r"(ba));
                asm("ld.shared.v4.u32 {%0,%1,%2,%3}, [%4];"
                    : "=r"(f1.x), "=r"(f1.y), "=r"(f1.z), "=r"(f1.w) : "r"(ba + 512));
                MMA_BF16(acc[nt], a[0][0], f0.x, f0.y);   // hi*hi ks0
                MMA_BF16(acc[nt], a[0][1], f1.x, f1.y);   // hi*hi ks1
                MMA_BF16(acc[nt], a[0][0], f0.z, f0.w);   // hi*lo ks0
                MMA_BF16(acc[nt], a[0][1], f1.z, f1.w);   // hi*lo ks1
                MMA_BF16(acc[nt], a[1][0], f0.x, f0.y);   // lo*hi ks0
                MMA_BF16(acc[nt], a[1][1], f1.x, f1.y);   // lo*hi ks1
            }

            // direct fragment stores: t = n, d = d0 + r (+8)
#pragma unroll
            for (int nt = 0; nt < PH_NT; nt++) {
                const int n = (p * PH_NT + nt) * 8 + qp * 2;
                ob[(size_t)n * D_DIM]           = acc[nt][0];
                ob[(size_t)(n + 1) * D_DIM]     = acc[nt][1];
                ob[(size_t)n * D_DIM + 8]       = acc[nt][2];
                ob[(size_t)(n + 1) * D_DIM + 8] = acc[nt][3];
            }
        }
    }
}

extern "C" void kernel_launch(void* const* d_in, const int* in_sizes, int n_in,
                              void* d_out, int out_size) {
    const float* x  = (const float*)d_in[0];   // [256, 336, 512]
    const float* W  = (const float*)d_in[1];   // [24, 1]
    const float* bs = (const float*)d_in[2];   // [1]
    float* out = (float*)d_out;                // [256, 168, 512]

    const int n_ctas = (B_DIM * D_DIM) / 64;   // 2048
    ar_ws_kernel<<<n_ctas, THREADS>>>(x, W, bs, out);
}